// round 6
// baseline (speedup 1.0000x reference)
#include <cuda_runtime.h>

// DrQ-v2 random-shift augmentation.
// x: [B=32, L=16, c=9, h=84, w=84] fp32  -> 4608 planes of 84x84
// shift: [512, 2] int32 (sx, sy) in [0, 8]
// out[n,c,i,j] = x[n,c, clamp(i + sy - 4, 0, 83), clamp(j + sx - 4, 0, 83)]
//
// All global traffic is aligned LDG.128 / STG.128. The +/-4-column shift is
// a component rotate by r = dx & 3, specialized at compile time per r via a
// block-uniform switch (dx is constant per block). Edge replication is a
// cheap fixup on the first/last vec of each row only.

#define PADV 4
#define NC 9
#define HH 84
#define WW 84
#define WV (WW / 4)          // 21 float4 per row
#define NVEC (HH * WV)       // 1764 float4 per plane
#define NPLANES (512 * NC)   // 4608
#define TPB 256

template<int R, int K0, int K1>
__device__ __forceinline__ void do_batch(
    const float4* __restrict__ xin4, float4* __restrict__ o4,
    const int t, const int dx, const int dy)
{
    float4 lo[K1 - K0], hi[K1 - K0];

    // ---- front-batched aligned vector loads ----
    #pragma unroll
    for (int k = K0; k < K1; k++) {
        int vec = t + k * TPB;
        if (vec >= NVEC) vec = NVEC - 1;   // safe dummy for tail lanes

        const int i  = vec / WV;
        const int jv = vec - i * WV;

        int si = i + dy;
        si = si < 0 ? 0 : (si > HH - 1 ? HH - 1 : si);
        const float4* __restrict__ rowv = xin4 + si * WV;

        const int base = 4 * jv + dx;                      // [-4, 84]
        int b0 = base;
        b0 = b0 < 0 ? 0 : (b0 > 83 ? 83 : b0);
        lo[k - K0] = __ldcs(&rowv[b0 >> 2]);

        if (R != 0) {
            int b3 = base + 3;
            b3 = b3 < 0 ? 0 : (b3 > 83 ? 83 : b3);
            hi[k - K0] = __ldcs(&rowv[b3 >> 2]);
        } else {
            hi[k - K0] = lo[k - K0];       // provably identical when r==0
        }
    }

    // ---- static rotate + edge fixups, coalesced streaming stores ----
    #pragma unroll
    for (int k = K0; k < K1; k++) {
        const int vec = t + k * TPB;
        if (vec < NVEC) {
            const int i  = vec / WV;
            const int jv = vec - i * WV;

            const float4 L = lo[k - K0];
            const float4 H = hi[k - K0];

            float4 f;
            if (R == 0)      { f.x = L.x; f.y = L.y; f.z = L.z; f.w = L.w; }
            else if (R == 1) { f.x = L.y; f.y = L.z; f.z = L.w; f.w = H.x; }
            else if (R == 2) { f.x = L.z; f.y = L.w; f.z = H.x; f.w = H.y; }
            else             { f.x = L.w; f.y = H.x; f.z = H.y; f.w = H.z; }

            if (dx < 0) {                  // uniform branch
                if (jv == 0) {             // L.x == row[0] here (b0 clamped)
                    f.x = L.x;             // m=0 < -dx always when dx<0
                    if (dx < -1) f.y = L.x;
                    if (dx < -2) f.z = L.x;
                    if (dx < -3) f.w = L.x;
                }
            } else if (dx > 0) {           // uniform branch
                if (jv == WV - 1) {        // H.w == row[83] here (b3 clamped)
                    f.w = H.w;             // m=3 > 3-dx always when dx>0
                    if (dx > 1) f.z = H.w;
                    if (dx > 2) f.y = H.w;
                    if (dx > 3) f.x = H.w;
                }
            }

            __stcs(&o4[vec], f);
        }
    }
}

template<int R>
__device__ __forceinline__ void run_plane(
    const float4* __restrict__ xin4, float4* __restrict__ o4,
    const int t, const int dx, const int dy)
{
    do_batch<R, 0, 4>(xin4, o4, t, dx, dy);
    do_batch<R, 4, 7>(xin4, o4, t, dx, dy);
}

__global__ __launch_bounds__(TPB) void drq_shift_kernel(
    const float* __restrict__ x,
    const int* __restrict__ shift,
    float* __restrict__ out)
{
    const int p = blockIdx.x;          // plane index = n * 9 + c
    const int n = p / NC;              // image index
    const int dx = __ldg(&shift[2 * n]) - PADV;      // [-4, 4]
    const int dy = __ldg(&shift[2 * n + 1]) - PADV;  // [-4, 4]

    const float4* __restrict__ xin4 =
        reinterpret_cast<const float4*>(x + (size_t)p * (HH * WW));
    float4* __restrict__ o4 =
        reinterpret_cast<float4*>(out + (size_t)p * (HH * WW));

    const int t = threadIdx.x;

    switch (dx & 3) {                  // block-uniform dispatch
        case 0: run_plane<0>(xin4, o4, t, dx, dy); break;
        case 1: run_plane<1>(xin4, o4, t, dx, dy); break;
        case 2: run_plane<2>(xin4, o4, t, dx, dy); break;
        default: run_plane<3>(xin4, o4, t, dx, dy); break;
    }
}

extern "C" void kernel_launch(void* const* d_in, const int* in_sizes, int n_in,
                              void* d_out, int out_size)
{
    const float* x     = (const float*)d_in[0];
    const int*   shift = (const int*)d_in[1];
    float*       out   = (float*)d_out;

    drq_shift_kernel<<<NPLANES, TPB>>>(x, shift, out);
}